// round 2
// baseline (speedup 1.0000x reference)
#include <cuda_runtime.h>
#include <cuda_fp16.h>

#define SEQ   8192
#define NN    1024
#define DD    64
#define QSZ   256
#define BOT   40
#define INNER 512
#define NTILES 128   // SEQ / 64

// ------------------------- scratch (no allocs allowed) -----------------------
__device__ __half g_q[(size_t)4 * SEQ * DD];    // [b][s][d], pre-scaled by 0.125*log2e
__device__ __half g_k[(size_t)4 * SEQ * DD];    // [b][s][d]
__device__ __half g_vt[(size_t)4 * DD * SEQ];   // [b][d][s]  (V transposed)
__device__ float  g_attn[(size_t)4096 * INNER]; // [b*1024+n][h*64+d]

__device__ __forceinline__ float ex2f(float x) {
    float y;
    asm("ex2.approx.ftz.f32 %0, %1;" : "=f"(y) : "f"(x));
    return y;
}

__device__ __forceinline__ unsigned packh2(float a, float b) {
    __half2 h = __floats2half2_rn(a, b);
    return *reinterpret_cast<unsigned*>(&h);
}

__device__ __forceinline__ void mma16816(float (&c)[4], const unsigned (&a)[4],
                                         unsigned b0, unsigned b1) {
    asm volatile(
        "mma.sync.aligned.m16n8k16.row.col.f32.f16.f16.f32 "
        "{%0,%1,%2,%3}, {%4,%5,%6,%7}, {%8,%9}, {%0,%1,%2,%3};\n"
        : "+f"(c[0]), "+f"(c[1]), "+f"(c[2]), "+f"(c[3])
        : "r"(a[0]), "r"(a[1]), "r"(a[2]), "r"(a[3]), "r"(b0), "r"(b1));
}

__device__ __forceinline__ void cp16(void* s, const void* g) {
    unsigned sa = (unsigned)__cvta_generic_to_shared(s);
    asm volatile("cp.async.cg.shared.global [%0], [%1], 16;\n" :: "r"(sa), "l"(g));
}

// ---------------------------------------------------------------------------
// Fused bottleneck projection: act(x @ w1) @ w2 per grid.y (0=q,1=k,2=v)
// ---------------------------------------------------------------------------
__global__ __launch_bounds__(256) void proj_kernel(
    const float* __restrict__ x,
    const float* __restrict__ wq1, const float* __restrict__ wq2,
    const float* __restrict__ wk1, const float* __restrict__ wk2,
    const float* __restrict__ wv1, const float* __restrict__ wv2) {
    __shared__ float sW[QSZ * BOT];   // phase A: w1 (256x40); phase B: w2 chunk (40x128)
    __shared__ float sB[32 * 44];     // bottleneck tile (padded)

    const int proj = blockIdx.y;
    const float* w1 = (proj == 0) ? wq1 : (proj == 1 ? wk1 : wv1);
    const float* w2 = (proj == 0) ? wq2 : (proj == 1 ? wk2 : wv2);
    const int row0 = blockIdx.x * 32;
    const int tid = threadIdx.x;
    const int r = tid >> 3;           // row in tile [0,32)
    const int tc = tid & 7;           // col thread [0,8)

#pragma unroll
    for (int i = 0; i < 40; i++) sW[tid + i * 256] = w1[tid + i * 256];
    __syncthreads();

    // ---- Phase A: bottleneck = x @ w1 (+ silu for k) ----
    {
        const float4* xr = reinterpret_cast<const float4*>(x + (size_t)(row0 + r) * QSZ);
        float acc[5] = {0.f, 0.f, 0.f, 0.f, 0.f};
#pragma unroll 4
        for (int k4 = 0; k4 < 64; k4++) {
            float4 xv = xr[k4];
            float xa[4] = {xv.x, xv.y, xv.z, xv.w};
            const float* w = sW + k4 * 4 * BOT + tc;
#pragma unroll
            for (int kk = 0; kk < 4; kk++)
#pragma unroll
                for (int i = 0; i < 5; i++)
                    acc[i] += xa[kk] * w[kk * BOT + i * 8];
        }
#pragma unroll
        for (int i = 0; i < 5; i++) {
            float v = acc[i];
            if (proj == 1) v = v / (1.0f + __expf(-v));  // silu
            sB[r * 44 + tc + 8 * i] = v;
        }
    }
    __syncthreads();

    float breg[BOT];
#pragma unroll
    for (int k = 0; k < BOT; k++) breg[k] = sB[r * 44 + k];

    const int cb = tc * 4;
    const int grow = row0 + r;
    const int bidx = grow >> 10;
    const int nidx = grow & 1023;

    // ---- Phase B: out = bottleneck @ w2, 4 column chunks of 128 ----
    for (int ch = 0; ch < 4; ch++) {
        __syncthreads();
#pragma unroll
        for (int i = 0; i < 5; i++) {
            int task = tid + i * 256;         // 1280 float4 loads (40x128 floats)
            int kk = task >> 5;
            int c4 = (task & 31) * 4;
            *reinterpret_cast<float4*>(sW + kk * 128 + c4) =
                *reinterpret_cast<const float4*>(w2 + (size_t)kk * INNER + ch * 128 + c4);
        }
        __syncthreads();
#pragma unroll
        for (int i = 0; i < 4; i++) {
            int lcol = cb + i * 32;
            int col = ch * 128 + lcol;
            float ax = 0.f, ay = 0.f, az = 0.f, aw = 0.f;
#pragma unroll
            for (int k = 0; k < BOT; k++) {
                float4 w = *reinterpret_cast<const float4*>(sW + k * 128 + lcol);
                float bv = breg[k];
                ax += bv * w.x; ay += bv * w.y; az += bv * w.z; aw += bv * w.w;
            }
            int h = col >> 6, d = col & 63;
            if (proj == 0) {
                const float s = 0.125f * 1.4426950408889634f;  // d^-0.5 * log2(e)
                __half2* dst = reinterpret_cast<__half2*>(
                    g_q + ((size_t)bidx * SEQ + h * NN + nidx) * DD + d);
                dst[0] = __floats2half2_rn(ax * s, ay * s);
                dst[1] = __floats2half2_rn(az * s, aw * s);
            } else if (proj == 1) {
                __half2* dst = reinterpret_cast<__half2*>(
                    g_k + ((size_t)bidx * SEQ + h * NN + nidx) * DD + d);
                dst[0] = __floats2half2_rn(ax, ay);
                dst[1] = __floats2half2_rn(az, aw);
            } else {
                size_t base = ((size_t)bidx * DD + d) * SEQ + h * NN + nidx;
                g_vt[base]           = __float2half_rn(ax);
                g_vt[base + SEQ]     = __float2half_rn(ay);
                g_vt[base + 2 * SEQ] = __float2half_rn(az);
                g_vt[base + 3 * SEQ] = __float2half_rn(aw);
            }
        }
    }
}

// ---------------------------------------------------------------------------
// Flash attention: seq 8192, d=64, Br=128 (4 warps x 32 rows), Bc=64.
// ---------------------------------------------------------------------------
__global__ __launch_bounds__(128) void attn_kernel() {
    __shared__ __half sK[2][64 * 72];
    __shared__ __half sV[2][64 * 72];

    const int b = blockIdx.y;
    const int row0 = blockIdx.x * 128;
    const int tid = threadIdx.x;
    const int warp = tid >> 5, lane = tid & 31;
    const int gi = lane >> 2, tig = lane & 3;

    const __half* kbase = g_k + (size_t)b * SEQ * DD;
    const __half* vbase = g_vt + (size_t)b * DD * SEQ;

    // prologue: load tile 0 into buf 0
    {
#pragma unroll
        for (int i = 0; i < 4; i++) {
            int t = tid + i * 128;
            int row = t >> 3, seg = t & 7;
            cp16(&sK[0][row * 72 + seg * 8], kbase + (size_t)row * DD + seg * 8);
            cp16(&sV[0][row * 72 + seg * 8], vbase + (size_t)row * SEQ + seg * 8);
        }
        asm volatile("cp.async.commit_group;\n");
    }

    // Q fragments straight from gmem (mma A layout)
    unsigned qf[2][4][4];
    const __half* qb = g_q + ((size_t)b * SEQ + row0 + warp * 32) * DD;
#pragma unroll
    for (int rb = 0; rb < 2; rb++)
#pragma unroll
        for (int kc = 0; kc < 4; kc++) {
            int rr = rb * 16 + gi;
            int cc = kc * 16 + tig * 2;
            qf[rb][kc][0] = *reinterpret_cast<const unsigned*>(qb + rr * DD + cc);
            qf[rb][kc][1] = *reinterpret_cast<const unsigned*>(qb + (rr + 8) * DD + cc);
            qf[rb][kc][2] = *reinterpret_cast<const unsigned*>(qb + rr * DD + cc + 8);
            qf[rb][kc][3] = *reinterpret_cast<const unsigned*>(qb + (rr + 8) * DD + cc + 8);
        }

    float O[2][8][4];
#pragma unroll
    for (int rb = 0; rb < 2; rb++)
#pragma unroll
        for (int dt = 0; dt < 8; dt++)
#pragma unroll
            for (int q = 0; q < 4; q++) O[rb][dt][q] = 0.f;

    float m[2][2] = {{-1e30f, -1e30f}, {-1e30f, -1e30f}};
    float l[2][2] = {{0.f, 0.f}, {0.f, 0.f}};

    int buf = 0;
    for (int jt = 0; jt < NTILES; jt++) {
        if (jt + 1 < NTILES) {
            const __half* kp = kbase + (size_t)(jt + 1) * 64 * DD;
            const __half* vp = vbase + (jt + 1) * 64;
#pragma unroll
            for (int i = 0; i < 4; i++) {
                int t = tid + i * 128;
                int row = t >> 3, seg = t & 7;
                cp16(&sK[buf ^ 1][row * 72 + seg * 8], kp + (size_t)row * DD + seg * 8);
                cp16(&sV[buf ^ 1][row * 72 + seg * 8], vp + (size_t)row * SEQ + seg * 8);
            }
            asm volatile("cp.async.commit_group;\n");
            asm volatile("cp.async.wait_group 1;\n");
        } else {
            asm volatile("cp.async.wait_group 0;\n");
        }
        __syncthreads();

        // ---- S = Q @ K^T ----
        float S[2][8][4];
#pragma unroll
        for (int rb = 0; rb < 2; rb++)
#pragma unroll
            for (int nt = 0; nt < 8; nt++)
#pragma unroll
                for (int q = 0; q < 4; q++) S[rb][nt][q] = 0.f;

#pragma unroll
        for (int nt = 0; nt < 8; nt++) {
            unsigned kb0[4], kb1[4];
            const __half* kr = &sK[buf][(nt * 8 + gi) * 72 + tig * 2];
#pragma unroll
            for (int kc = 0; kc < 4; kc++) {
                kb0[kc] = *reinterpret_cast<const unsigned*>(kr + kc * 16);
                kb1[kc] = *reinterpret_cast<const unsigned*>(kr + kc * 16 + 8);
            }
#pragma unroll
            for (int rb = 0; rb < 2; rb++)
#pragma unroll
                for (int kc = 0; kc < 4; kc++)
                    mma16816(S[rb][nt], qf[rb][kc], kb0[kc], kb1[kc]);
        }

        // ---- online softmax (S already in log2 domain via Q pre-scale) ----
#pragma unroll
        for (int rb = 0; rb < 2; rb++) {
#pragma unroll
            for (int h2 = 0; h2 < 2; h2++) {
                float tm = -1e30f;
#pragma unroll
                for (int nt = 0; nt < 8; nt++)
                    tm = fmaxf(tm, fmaxf(S[rb][nt][2 * h2], S[rb][nt][2 * h2 + 1]));
                tm = fmaxf(tm, __shfl_xor_sync(0xffffffffu, tm, 1));
                tm = fmaxf(tm, __shfl_xor_sync(0xffffffffu, tm, 2));
                float mn = fmaxf(m[rb][h2], tm);
                float al = ex2f(m[rb][h2] - mn);
                m[rb][h2] = mn;
                l[rb][h2] *= al;
#pragma unroll
                for (int dt = 0; dt < 8; dt++) {
                    O[rb][dt][2 * h2]     *= al;
                    O[rb][dt][2 * h2 + 1] *= al;
                }
            }
#pragma unroll
            for (int nt = 0; nt < 8; nt++)
#pragma unroll
                for (int q = 0; q < 4; q++) {
                    float p = ex2f(S[rb][nt][q] - m[rb][q >> 1]);
                    l[rb][q >> 1] += p;
                    S[rb][nt][q] = p;
                }
        }

        // ---- P fragments (reuse S accumulator layout) ----
        unsigned pa[2][4][4];
#pragma unroll
        for (int rb = 0; rb < 2; rb++)
#pragma unroll
            for (int kc = 0; kc < 4; kc++) {
                pa[rb][kc][0] = packh2(S[rb][2 * kc][0],     S[rb][2 * kc][1]);
                pa[rb][kc][1] = packh2(S[rb][2 * kc][2],     S[rb][2 * kc][3]);
                pa[rb][kc][2] = packh2(S[rb][2 * kc + 1][0], S[rb][2 * kc + 1][1]);
                pa[rb][kc][3] = packh2(S[rb][2 * kc + 1][2], S[rb][2 * kc + 1][3]);
            }

        // ---- O += P @ V  (V stored transposed: contiguous half2 B frags) ----
#pragma unroll
        for (int dt = 0; dt < 8; dt++) {
            unsigned vb0[4], vb1[4];
            const __half* vr = &sV[buf][(dt * 8 + gi) * 72 + tig * 2];
#pragma unroll
            for (int kc = 0; kc < 4; kc++) {
                vb0[kc] = *reinterpret_cast<const unsigned*>(vr + kc * 16);
                vb1[kc] = *reinterpret_cast<const unsigned*>(vr + kc * 16 + 8);
            }
#pragma unroll
            for (int rb = 0; rb < 2; rb++)
#pragma unroll
                for (int kc = 0; kc < 4; kc++)
                    mma16816(O[rb][dt], pa[rb][kc], vb0[kc], vb1[kc]);
        }
        __syncthreads();
        buf ^= 1;
    }

    // ---- epilogue: normalize + store to g_attn (unsplit layout) ----
#pragma unroll
    for (int rb = 0; rb < 2; rb++) {
#pragma unroll
        for (int h2 = 0; h2 < 2; h2++) {
            float lt = l[rb][h2];
            lt += __shfl_xor_sync(0xffffffffu, lt, 1);
            lt += __shfl_xor_sync(0xffffffffu, lt, 2);
            float inv = 1.0f / lt;
            int srow = row0 + warp * 32 + rb * 16 + gi + h2 * 8;
            int h = srow >> 10, n = srow & 1023;
            float* orow = g_attn + ((size_t)((b << 10) | n)) * INNER + h * 64;
#pragma unroll
            for (int dt = 0; dt < 8; dt++) {
                float2 o2 = make_float2(O[rb][dt][2 * h2] * inv,
                                        O[rb][dt][2 * h2 + 1] * inv);
                *reinterpret_cast<float2*>(orow + dt * 8 + tig * 2) = o2;
            }
        }
    }
}

// ---------------------------------------------------------------------------
// Output projection: out = g_attn (4096x512) @ wo (512x256) + bo   (fp32)
// ---------------------------------------------------------------------------
__global__ __launch_bounds__(256) void out_gemm(
    const float* __restrict__ wo, const float* __restrict__ bo,
    float* __restrict__ out) {
    __shared__ float As[64][32];
    __shared__ float Bs[32][64];

    const int bm0 = blockIdx.x * 64;
    const int bn0 = blockIdx.y * 64;
    const int tid = threadIdx.x;
    const int tx = tid & 15, ty = tid >> 4;

    float acc[4][4];
#pragma unroll
    for (int i = 0; i < 4; i++)
#pragma unroll
        for (int j = 0; j < 4; j++) acc[i][j] = 0.f;

    for (int kb = 0; kb < 16; kb++) {
#pragma unroll
        for (int i = 0; i < 2; i++) {
            int t = tid + i * 256;
            int ra = t >> 3, ca = (t & 7) * 4;
            *reinterpret_cast<float4*>(&As[ra][ca]) =
                *reinterpret_cast<const float4*>(g_attn + (size_t)(bm0 + ra) * 512 + kb * 32 + ca);
            int rb2 = t >> 4, cb2 = (t & 15) * 4;
            *reinterpret_cast<float4*>(&Bs[rb2][cb2]) =
                *reinterpret_cast<const float4*>(wo + (size_t)(kb * 32 + rb2) * 256 + bn0 + cb2);
        }
        __syncthreads();
#pragma unroll
        for (int k = 0; k < 32; k++) {
            float a[4];
#pragma unroll
            for (int i = 0; i < 4; i++) a[i] = As[ty * 4 + i][k];
            float4 bv = *reinterpret_cast<const float4*>(&Bs[k][tx * 4]);
#pragma unroll
            for (int i = 0; i < 4; i++) {
                acc[i][0] += a[i] * bv.x;
                acc[i][1] += a[i] * bv.y;
                acc[i][2] += a[i] * bv.z;
                acc[i][3] += a[i] * bv.w;
            }
        }
        __syncthreads();
    }

    float4 bias = *reinterpret_cast<const float4*>(bo + bn0 + tx * 4);
#pragma unroll
    for (int i = 0; i < 4; i++) {
        float4 o;
        o.x = acc[i][0] + bias.x;
        o.y = acc[i][1] + bias.y;
        o.z = acc[i][2] + bias.z;
        o.w = acc[i][3] + bias.w;
        *reinterpret_cast<float4*>(out + (size_t)(bm0 + ty * 4 + i) * 256 + bn0 + tx * 4) = o;
    }
}

// ---------------------------------------------------------------------------
extern "C" void kernel_launch(void* const* d_in, const int* in_sizes, int n_in,
                              void* d_out, int out_size) {
    const float* x   = (const float*)d_in[0];
    const float* wq1 = (const float*)d_in[1];
    const float* wq2 = (const float*)d_in[2];
    const float* wk1 = (const float*)d_in[3];
    const float* wk2 = (const float*)d_in[4];
    const float* wv1 = (const float*)d_in[5];
    const float* wv2 = (const float*)d_in[6];
    const float* wo  = (const float*)d_in[7];
    const float* bo  = (const float*)d_in[8];
    float* out = (float*)d_out;

    proj_kernel<<<dim3(128, 3), 256>>>(x, wq1, wq2, wk1, wk2, wv1, wv2);
    attn_kernel<<<dim3(64, 4), 128>>>();
    out_gemm<<<dim3(64, 4), 256>>>(wo, bo, out);
}